// round 14
// baseline (speedup 1.0000x reference)
#include <cuda_runtime.h>
#include <cuda_bf16.h>
#include <cuda_fp16.h>
#include <math.h>
#include <stdint.h>

// Problem dims (fixed by the reference)
#define B_DIM 8
#define C_DIM 512
#define N_DIM 4096   // W*H = 64*64
#define HALF_N 2048  // split-K half for m1

#define KC 32        // k-chunk
#define LDT 40       // smem tile row stride in bf16 (pad 32 -> 40, conflict-free ldmatrix)
#define TILE_BYTES (128 * LDT * 2)        // 10240
#define STAGE_BYTES (4 * TILE_BYTES)      // 40960 (Ah, Al, Bh, Bl)
#define SMEM_TOTAL (2 * STAGE_BYTES)      // 81920  (m1)
#define STAGE2_BYTES (2 * TILE_BYTES)     // 20480 (A, B) fp16 single-term
#define SMEM_OUT (2 * STAGE2_BYTES)       // 40960  (out)

// ---------------------------------------------------------------------------
// Scratch (device globals — no allocation allowed)
// ---------------------------------------------------------------------------
__device__ __align__(16) __nv_bfloat16 g_xh[(size_t)B_DIM * C_DIM * N_DIM];  // x hi   [b][c][n]
__device__ __align__(16) __nv_bfloat16 g_xl[(size_t)B_DIM * C_DIM * N_DIM];  // x lo
__device__ __align__(16) __half        g_xtf[(size_t)B_DIM * N_DIM * C_DIM]; // x^T fp16 [b][n][c]
__device__ __align__(16) __nv_bfloat16 g_qh[(size_t)C_DIM * N_DIM];          // q hi   [d][n]
__device__ __align__(16) __nv_bfloat16 g_ql[(size_t)C_DIM * N_DIM];          // q lo
__device__ __align__(16) __half        g_Pf[(size_t)B_DIM * C_DIM * C_DIM];  // P fp16 [b][c][e]
__device__ float g_M1[(size_t)2 * B_DIM * C_DIM * C_DIM];   // split-K halves [h][b][c][d]
__device__ float g_att[(size_t)B_DIM * C_DIM * C_DIM];
__device__ float g_ob[(size_t)B_DIM * C_DIM];
__device__ float g_qs[C_DIM];

// ---------------------------------------------------------------------------
// PTX helpers (arch-generic: ldmatrix / mma.sync / cp.async)
// ---------------------------------------------------------------------------
__device__ __forceinline__ uint32_t smem_u32(const void* p) {
    uint32_t a;
    asm("{ .reg .u64 t; cvta.to.shared.u64 t, %1; cvt.u32.u64 %0, t; }"
        : "=r"(a) : "l"(p));
    return a;
}

__device__ __forceinline__ void ldsm4(uint32_t r[4], uint32_t addr) {
    asm volatile("ldmatrix.sync.aligned.m8n8.x4.shared.b16 {%0,%1,%2,%3}, [%4];"
                 : "=r"(r[0]), "=r"(r[1]), "=r"(r[2]), "=r"(r[3]) : "r"(addr));
}

__device__ __forceinline__ void mma16816(float c[4], const uint32_t a[4],
                                         const uint32_t b[2]) {
    asm volatile(
        "mma.sync.aligned.m16n8k16.row.col.f32.bf16.bf16.f32 "
        "{%0,%1,%2,%3}, {%4,%5,%6,%7}, {%8,%9}, {%0,%1,%2,%3};"
        : "+f"(c[0]), "+f"(c[1]), "+f"(c[2]), "+f"(c[3])
        : "r"(a[0]), "r"(a[1]), "r"(a[2]), "r"(a[3]), "r"(b[0]), "r"(b[1]));
}

__device__ __forceinline__ void mma16816_f16(float c[4], const uint32_t a[4],
                                             const uint32_t b[2]) {
    asm volatile(
        "mma.sync.aligned.m16n8k16.row.col.f32.f16.f16.f32 "
        "{%0,%1,%2,%3}, {%4,%5,%6,%7}, {%8,%9}, {%0,%1,%2,%3};"
        : "+f"(c[0]), "+f"(c[1]), "+f"(c[2]), "+f"(c[3])
        : "r"(a[0]), "r"(a[1]), "r"(a[2]), "r"(a[3]), "r"(b[0]), "r"(b[1]));
}

#define CP_ASYNC16(dst, src)                                            \
    asm volatile("cp.async.cg.shared.global [%0], [%1], 16;"            \
                 :: "r"(dst), "l"(src) : "memory")
#define CP_COMMIT asm volatile("cp.async.commit_group;" ::: "memory")
#define CP_WAIT1  asm volatile("cp.async.wait_group 1;" ::: "memory")
#define CP_WAIT0  asm volatile("cp.async.wait_group 0;" ::: "memory")

// Stage one 128 x KC 16-bit tile: 512 x 16B transfers, 2 per thread.
__device__ __forceinline__ void stage_tile(
    uint32_t dstBase, const void* __restrict__ src16,
    int ld, int k0, int tid)
{
    const __nv_bfloat16* src = (const __nv_bfloat16*)src16;
    #pragma unroll
    for (int u = 0; u < 2; u++) {
        int tr  = tid * 2 + u;
        int row = tr >> 2, seg = tr & 3;
        uint32_t dst = dstBase + (uint32_t)row * (LDT * 2) + seg * 16;
        const __nv_bfloat16* s = src + (size_t)row * ld + k0 + seg * 8;
        CP_ASYNC16(dst, (const void*)__cvta_generic_to_global(s));
    }
}

// Compute one KC=32 chunk: 3 bf16 terms (hh, hl, lh) into fp32 acc.
__device__ __forceinline__ void compute_stage(
    uint32_t as_h, uint32_t as_l, uint32_t bs_h, uint32_t bs_l,
    float acc[4][4][4], int lane, int warpM, int warpN)
{
    const int rowA = lane & 15;
    const int colA = (lane >> 4) << 3;
    const int tile = lane >> 3;
    const int rowB = (lane & 7) + ((tile >> 1) << 3);
    const int colB = (tile & 1) << 3;

    #pragma unroll
    for (int ks = 0; ks < KC; ks += 16) {
        uint32_t a[4][4], bb[4][2];
        #pragma unroll
        for (int mi = 0; mi < 4; mi++)
            ldsm4(a[mi], as_h + (uint32_t)(warpM + mi * 16 + rowA) * (LDT * 2)
                               + (colA + ks) * 2);
        #pragma unroll
        for (int njp = 0; njp < 2; njp++) {
            uint32_t r[4];
            ldsm4(r, bs_h + (uint32_t)(warpN + njp * 16 + rowB) * (LDT * 2)
                          + (colB + ks) * 2);
            bb[njp * 2][0] = r[0];  bb[njp * 2][1] = r[1];
            bb[njp * 2 + 1][0] = r[2];  bb[njp * 2 + 1][1] = r[3];
        }
        #pragma unroll
        for (int mi = 0; mi < 4; mi++)
            #pragma unroll
            for (int nj = 0; nj < 4; nj++) mma16816(acc[mi][nj], a[mi], bb[nj]);
        {
            uint32_t al[4][4];
            #pragma unroll
            for (int mi = 0; mi < 4; mi++)
                ldsm4(al[mi], as_l + (uint32_t)(warpM + mi * 16 + rowA) * (LDT * 2)
                                   + (colA + ks) * 2);
            #pragma unroll
            for (int mi = 0; mi < 4; mi++)
                #pragma unroll
                for (int nj = 0; nj < 4; nj++) mma16816(acc[mi][nj], al[mi], bb[nj]);
        }
        #pragma unroll
        for (int njp = 0; njp < 2; njp++) {
            uint32_t r[4];
            ldsm4(r, bs_l + (uint32_t)(warpN + njp * 16 + rowB) * (LDT * 2)
                          + (colB + ks) * 2);
            bb[njp * 2][0] = r[0];  bb[njp * 2][1] = r[1];
            bb[njp * 2 + 1][0] = r[2];  bb[njp * 2 + 1][1] = r[3];
        }
        #pragma unroll
        for (int mi = 0; mi < 4; mi++)
            #pragma unroll
            for (int nj = 0; nj < 4; nj++) mma16816(acc[mi][nj], a[mi], bb[nj]);
    }
}

// Single-term fp16 chunk: 16 MMAs per k16.
__device__ __forceinline__ void compute_stage_f16(
    uint32_t as, uint32_t bs, float acc[4][4][4], int lane, int warpM, int warpN)
{
    const int rowA = lane & 15;
    const int colA = (lane >> 4) << 3;
    const int tile = lane >> 3;
    const int rowB = (lane & 7) + ((tile >> 1) << 3);
    const int colB = (tile & 1) << 3;

    #pragma unroll
    for (int ks = 0; ks < KC; ks += 16) {
        uint32_t a[4][4], bb[4][2];
        #pragma unroll
        for (int mi = 0; mi < 4; mi++)
            ldsm4(a[mi], as + (uint32_t)(warpM + mi * 16 + rowA) * (LDT * 2)
                             + (colA + ks) * 2);
        #pragma unroll
        for (int njp = 0; njp < 2; njp++) {
            uint32_t r[4];
            ldsm4(r, bs + (uint32_t)(warpN + njp * 16 + rowB) * (LDT * 2)
                        + (colB + ks) * 2);
            bb[njp * 2][0] = r[0];  bb[njp * 2][1] = r[1];
            bb[njp * 2 + 1][0] = r[2];  bb[njp * 2 + 1][1] = r[3];
        }
        #pragma unroll
        for (int mi = 0; mi < 4; mi++)
            #pragma unroll
            for (int nj = 0; nj < 4; nj++) mma16816_f16(acc[mi][nj], a[mi], bb[nj]);
    }
}

// bf16 3-term mainloop over k-range [kbeg, kbeg+K).
__device__ __forceinline__ void gemm_mainloop(
    uint32_t sb, const __nv_bfloat16* Ah, const __nv_bfloat16* Al,
    const __nv_bfloat16* Bh, const __nv_bfloat16* Bl,
    int lda, int ldb, int kbeg, int K, float acc[4][4][4],
    int tid, int lane, int warpM, int warpN)
{
    const uint32_t st[2] = { sb, sb + STAGE_BYTES };
    const int nk = K / KC;

    stage_tile(st[0],                  Ah, lda, kbeg, tid);
    stage_tile(st[0] + TILE_BYTES,     Al, lda, kbeg, tid);
    stage_tile(st[0] + 2 * TILE_BYTES, Bh, ldb, kbeg, tid);
    stage_tile(st[0] + 3 * TILE_BYTES, Bl, ldb, kbeg, tid);
    CP_COMMIT;

    for (int i = 0; i < nk; i++) {
        if (i + 1 < nk) {
            uint32_t d = st[(i + 1) & 1];
            int k0 = kbeg + (i + 1) * KC;
            stage_tile(d,                  Ah, lda, k0, tid);
            stage_tile(d + TILE_BYTES,     Al, lda, k0, tid);
            stage_tile(d + 2 * TILE_BYTES, Bh, ldb, k0, tid);
            stage_tile(d + 3 * TILE_BYTES, Bl, ldb, k0, tid);
            CP_COMMIT;
            CP_WAIT1;
        } else {
            CP_WAIT0;
        }
        __syncthreads();
        uint32_t s = st[i & 1];
        compute_stage(s, s + TILE_BYTES, s + 2 * TILE_BYTES, s + 3 * TILE_BYTES,
                      acc, lane, warpM, warpN);
        __syncthreads();
    }
}

// ---------------------------------------------------------------------------
// M1[h][b][c][d] = sum_{n in half h} x[b][c][n] * q[d][n]  (split-K HMMA)
// blockIdx.z = b*2 + h
// ---------------------------------------------------------------------------
__global__ __launch_bounds__(256, 2) void m1_mma()
{
    extern __shared__ char smem[];
    const uint32_t sb = smem_u32(smem);
    const int tid = threadIdx.x, lane = tid & 31, wid = tid >> 5;
    const int warpM = (wid >> 2) * 64, warpN = (wid & 3) * 32;
    const int bz = blockIdx.z;
    const int b = bz >> 1, h = bz & 1;
    const int m0 = blockIdx.y * 128, n0 = blockIdx.x * 128;

    float acc[4][4][4];
    #pragma unroll
    for (int i = 0; i < 4; i++)
        #pragma unroll
        for (int j = 0; j < 4; j++)
            #pragma unroll
            for (int k = 0; k < 4; k++) acc[i][j][k] = 0.f;

    const size_t xo = (size_t)b * C_DIM * N_DIM + (size_t)m0 * N_DIM;
    gemm_mainloop(sb, g_xh + xo, g_xl + xo,
                  g_qh + (size_t)n0 * N_DIM, g_ql + (size_t)n0 * N_DIM,
                  N_DIM, N_DIM, h * HALF_N, HALF_N, acc, tid, lane, warpM, warpN);

    const int gid = lane >> 2, tig = lane & 3;
    float* C = g_M1 + ((size_t)(h * B_DIM + b) * C_DIM + m0) * C_DIM + n0;
    #pragma unroll
    for (int mi = 0; mi < 4; mi++) {
        #pragma unroll
        for (int nj = 0; nj < 4; nj++) {
            int r = warpM + mi * 16 + gid;
            int c = warpN + nj * 8 + 2 * tig;
            *reinterpret_cast<float2*>(C + (size_t)r * C_DIM + c) =
                make_float2(acc[mi][nj][0], acc[mi][nj][1]);
            *reinterpret_cast<float2*>(C + (size_t)(r + 8) * C_DIM + c) =
                make_float2(acc[mi][nj][2], acc[mi][nj][3]);
        }
    }
}

// ---------------------------------------------------------------------------
// y[b][c][n] = gamma*(sum_e P[b][c][e]*x[b][e][n] + ob[b][c]) + x[b][c][n]
// Single-term fp16 HMMA (error ~2^-12, not softmax-amplified).
// ---------------------------------------------------------------------------
__global__ __launch_bounds__(256, 2) void out_mma(
    const float* __restrict__ x, const float* __restrict__ gamma,
    float* __restrict__ y)
{
    extern __shared__ char smem[];
    const uint32_t sb = smem_u32(smem);
    const int tid = threadIdx.x, lane = tid & 31, wid = tid >> 5;
    const int warpM = (wid >> 2) * 64, warpN = (wid & 3) * 32;
    const int b = blockIdx.z, m0 = blockIdx.y * 128, n0 = blockIdx.x * 128;

    float acc[4][4][4];
    #pragma unroll
    for (int i = 0; i < 4; i++)
        #pragma unroll
        for (int j = 0; j < 4; j++)
            #pragma unroll
            for (int k = 0; k < 4; k++) acc[i][j][k] = 0.f;

    const __half* A = g_Pf  + (size_t)b * C_DIM * C_DIM + (size_t)m0 * C_DIM;
    const __half* B = g_xtf + (size_t)b * N_DIM * C_DIM + (size_t)n0 * C_DIM;

    const uint32_t st[2] = { sb, sb + STAGE2_BYTES };
    const int nk = C_DIM / KC;   // 16

    stage_tile(st[0],              A, C_DIM, 0, tid);
    stage_tile(st[0] + TILE_BYTES, B, C_DIM, 0, tid);
    CP_COMMIT;

    for (int i = 0; i < nk; i++) {
        if (i + 1 < nk) {
            uint32_t d = st[(i + 1) & 1];
            int k0 = (i + 1) * KC;
            stage_tile(d,              A, C_DIM, k0, tid);
            stage_tile(d + TILE_BYTES, B, C_DIM, k0, tid);
            CP_COMMIT;
            CP_WAIT1;
        } else {
            CP_WAIT0;
        }
        __syncthreads();
        uint32_t s = st[i & 1];
        compute_stage_f16(s, s + TILE_BYTES, acc, lane, warpM, warpN);
        __syncthreads();
    }

    const int gid = lane >> 2, tig = lane & 3;
    const float g = *gamma;
    const float* xb = x + (size_t)b * C_DIM * N_DIM;
    float*       yb = y + (size_t)b * C_DIM * N_DIM;
    #pragma unroll
    for (int mi = 0; mi < 4; mi++) {
        #pragma unroll
        for (int nj = 0; nj < 4; nj++) {
            int r = m0 + warpM + mi * 16 + gid;
            int c = n0 + warpN + nj * 8 + 2 * tig;
            #pragma unroll
            for (int h = 0; h < 2; h++) {
                int rr = r + h * 8;
                float ob = g_ob[(size_t)b * C_DIM + rr];
                float2 xv = *reinterpret_cast<const float2*>(
                    xb + (size_t)rr * N_DIM + c);
                float2 o;
                o.x = fmaf(g, acc[mi][nj][h * 2 + 0] + ob, xv.x);
                o.y = fmaf(g, acc[mi][nj][h * 2 + 1] + ob, xv.y);
                *reinterpret_cast<float2*>(yb + (size_t)rr * N_DIM + c) = o;
            }
        }
    }
}

// ---------------------------------------------------------------------------
// split_x: x -> bf16 hi/lo [c][n] + fp16 x^T [n][c].  64x64 tiles, fully
// vectorized: float4 reads, 16B stores (2 per 16-value group per thread).
// Block 256 = (row r = t>>2 in tile, col group g = t&3 covering 16 cols).
// ---------------------------------------------------------------------------
__global__ __launch_bounds__(256) void split_x_kernel(const float* __restrict__ x)
{
    __shared__ float sx[64][65];
    const int b  = blockIdx.z;
    const int c0 = blockIdx.y * 64;
    const int n0 = blockIdx.x * 64;
    const int t  = threadIdx.x;
    const int r  = t >> 2;          // 0..63
    const int gcol = (t & 3) * 16;  // 0,16,32,48

    // Phase A: read 16 floats of row (c0+r), emit hi/lo, stash fp32.
    {
        const float* src = x + ((size_t)b * C_DIM + c0 + r) * N_DIM + n0 + gcol;
        __nv_bfloat16 h16[16], l16[16];
        #pragma unroll
        for (int u = 0; u < 4; u++) {
            float4 v = *reinterpret_cast<const float4*>(src + u * 4);
            float vv[4] = {v.x, v.y, v.z, v.w};
            #pragma unroll
            for (int k = 0; k < 4; k++) {
                float f = vv[k];
                __nv_bfloat16 hh = __float2bfloat16(f);
                h16[u * 4 + k] = hh;
                l16[u * 4 + k] = __float2bfloat16(f - __bfloat162float(hh));
                sx[r][gcol + u * 4 + k] = f;
            }
        }
        size_t o = ((size_t)b * C_DIM + c0 + r) * N_DIM + n0 + gcol;
        *reinterpret_cast<uint4*>(g_xh + o)     = reinterpret_cast<const uint4*>(h16)[0];
        *reinterpret_cast<uint4*>(g_xh + o + 8) = reinterpret_cast<const uint4*>(h16)[1];
        *reinterpret_cast<uint4*>(g_xl + o)     = reinterpret_cast<const uint4*>(l16)[0];
        *reinterpret_cast<uint4*>(g_xl + o + 8) = reinterpret_cast<const uint4*>(l16)[1];
    }
    __syncthreads();

    // Phase B: transposed — row r is now n-index, cols are c. fp16 out.
    {
        __half f16[16];
        #pragma unroll
        for (int k = 0; k < 16; k++)
            f16[k] = __float2half(sx[gcol + k][r]);
        size_t o = ((size_t)b * N_DIM + n0 + r) * C_DIM + c0 + gcol;
        *reinterpret_cast<uint4*>(g_xtf + o)     = reinterpret_cast<const uint4*>(f16)[0];
        *reinterpret_cast<uint4*>(g_xtf + o + 8) = reinterpret_cast<const uint4*>(f16)[1];
    }
}

// ---------------------------------------------------------------------------
// split_q + qsum fused: one block per q row d. hi/lo bf16 + row sum.
// ---------------------------------------------------------------------------
__global__ __launch_bounds__(256) void split_q_kernel(const float* __restrict__ q)
{
    const int d = blockIdx.x;
    const int t = threadIdx.x;
    const float* row = q + (size_t)d * N_DIM + t * 16;

    __nv_bfloat16 h16[16], l16[16];
    float s = 0.f;
    #pragma unroll
    for (int u = 0; u < 4; u++) {
        float4 v = *reinterpret_cast<const float4*>(row + u * 4);
        float vv[4] = {v.x, v.y, v.z, v.w};
        #pragma unroll
        for (int k = 0; k < 4; k++) {
            float f = vv[k];
            s += f;
            __nv_bfloat16 hh = __float2bfloat16(f);
            h16[u * 4 + k] = hh;
            l16[u * 4 + k] = __float2bfloat16(f - __bfloat162float(hh));
        }
    }
    size_t o = (size_t)d * N_DIM + t * 16;
    *reinterpret_cast<uint4*>(g_qh + o)     = reinterpret_cast<const uint4*>(h16)[0];
    *reinterpret_cast<uint4*>(g_qh + o + 8) = reinterpret_cast<const uint4*>(h16)[1];
    *reinterpret_cast<uint4*>(g_ql + o)     = reinterpret_cast<const uint4*>(l16)[0];
    *reinterpret_cast<uint4*>(g_ql + o + 8) = reinterpret_cast<const uint4*>(l16)[1];

    #pragma unroll
    for (int o2 = 16; o2 > 0; o2 >>= 1) s += __shfl_xor_sync(0xffffffffu, s, o2);
    __shared__ float red[8];
    if ((t & 31) == 0) red[t >> 5] = s;
    __syncthreads();
    if (t == 0) {
        float tt = 0.f;
        #pragma unroll
        for (int i = 0; i < 8; i++) tt += red[i];
        g_qs[d] = tt;
    }
}

// ---------------------------------------------------------------------------
// Fused E + softmax:
//   E[c][d] = sum_e Kw[c][e]*(M1a+M1b)[e][d] + kb[c]*qs[d];  att = softmax_d(E)
// Tile: 32 c-rows x FULL 512 d-cols (so softmax is CTA-local).
// Thread (warp w = rows 4w..4w+3, lane l = cols l+32j). Row softmax via shfl.
// ---------------------------------------------------------------------------
__global__ __launch_bounds__(256) void e_softmax(
    const float* __restrict__ kw, const float* __restrict__ kb)
{
    __shared__ float As[8][32];
    __shared__ float Bs[8][512];

    const int b  = blockIdx.y;
    const int m0 = blockIdx.x * 32;
    const int tid = threadIdx.x;
    const int wy  = tid >> 5;      // warp id 0..7 -> rows wy*4..wy*4+3
    const int lane = tid & 31;

    const float* M1a = g_M1 + (size_t)b * C_DIM * C_DIM;
    const float* M1b = g_M1 + (size_t)(B_DIM + b) * C_DIM * C_DIM;

    float acc[4][16];
    #pragma unroll
    for (int i = 0; i < 4; i++)
        #pragma unroll
        for (int j = 0; j < 16; j++) acc[i][j] = 0.f;

    for (int k0 = 0; k0 < C_DIM; k0 += 8) {
        // As[kk][m] = Kw[(m0+m)][k0+kk]
        {
            int kk = tid >> 5, m = tid & 31;
            As[kk][m] = kw[(size_t)(m0 + m) * C_DIM + k0 + kk];
        }
        // Bs[kk][n] = (M1a+M1b)[k0+kk][n], each thread 16 floats
        {
            int kk = tid >> 5;
            int nb = (tid & 31) * 16;
            size_t off = (size_t)(k0 + kk) * C_DIM + nb;
            #pragma unroll
            for (int u = 0; u < 4; u++) {
                float4 va = *reinterpret_cast<const float4*>(M1a + off + u * 4);
                float4 vb = *reinterpret_cast<const float4*>(M1b + off + u * 4);
                float4 vs;
                vs.x = va.x + vb.x;  vs.y = va.y + vb.y;
                vs.z = va.z + vb.z;  vs.w = va.w + vb.w;
                *reinterpret_cast<float4*>(&Bs[kk][nb + u * 4]) = vs;
            }
        }
        __syncthreads();

        #pragma unroll
        for (int kk = 0; kk < 8; kk++) {
            float a[4];
            #pragma unroll
            for (int i = 0; i < 4; i++) a[i] = As[kk][wy * 4 + i];
            #pragma unroll
            for (int j = 0; j < 16; j++) {
                float bv = Bs[kk][lane + 32 * j];
                #pragma unroll
                for (int i = 0; i < 4; i++)
                    acc[i][j] = fmaf(a[i], bv, acc[i][j]);
            }
        }
        __syncthreads();
    }

    // Epilogue: bias + row softmax + write att
    float qsv[16];
    #pragma unroll
    for (int j = 0; j < 16; j++) qsv[j] = g_qs[lane + 32 * j];

    float* att = g_att + (size_t)b * C_DIM * C_DIM;
    #pragma unroll
    for (int i = 0; i < 4; i++) {
        const int c = m0 + wy * 4 + i;
        const float bias = kb[c];
        float mx = -INFINITY;
        #pragma unroll
        for (int j = 0; j < 16; j++) {
            acc[i][j] = fmaf(bias, qsv[j], acc[i][j]);
            mx = fmaxf(mx, acc[i][j]);
        }
        #pragma unroll
        for (int o = 16; o > 0; o >>= 1)
            mx = fmaxf(mx, __shfl_xor_sync(0xffffffffu, mx, o));
        float sm = 0.f;
        #pragma unroll
        for (int j = 0; j < 16; j++) {
            float e = expf(acc[i][j] - mx);
            acc[i][j] = e;
            sm += e;
        }
        #pragma unroll
        for (int o = 16; o > 0; o >>= 1)
            sm += __shfl_xor_sync(0xffffffffu, sm, o);
        const float inv = 1.0f / sm;
        #pragma unroll
        for (int j = 0; j < 16; j++)
            att[(size_t)c * C_DIM + lane + 32 * j] = acc[i][j] * inv;
    }
}

// ---------------------------------------------------------------------------
// P[b][c][e] = sum_d att[b][d][c] * Vw[d][e]  (fp32 SGEMM, fp16 epilogue)
// ---------------------------------------------------------------------------
__global__ __launch_bounds__(256) void p_gemm(const float* __restrict__ vw)
{
    __shared__ float As[8][128];
    __shared__ float Bs[8][128];

    const int b  = blockIdx.z;
    const int m0 = blockIdx.y * 128;
    const int n0 = blockIdx.x * 128;
    const int tid = threadIdx.x;
    const int tx = tid & 15;
    const int ty = tid >> 4;

    const float* att = g_att + (size_t)b * C_DIM * C_DIM;

    float acc[8][8];
    #pragma unroll
    for (int i = 0; i < 8; i++)
        #pragma unroll
        for (int j = 0; j < 8; j++) acc[i][j] = 0.f;

    for (int k0 = 0; k0 < C_DIM; k0 += 8) {
        {
            int kk = tid >> 5;
            int m4 = (tid & 31) * 4;
            float4 av = *reinterpret_cast<const float4*>(
                att + (size_t)(k0 + kk) * C_DIM + m0 + m4);
            *reinterpret_cast<float4*>(&As[kk][m4]) = av;
        }
        {
            int kk = tid >> 5;
            int c4 = (tid & 31) * 4;
            float4 bv = *reinterpret_cast<const float4*>(
                vw + (size_t)(k0 + kk) * C_DIM + n0 + c4);
            *reinterpret_cast<float4*>(&Bs[kk][c4]) = bv;
        }
        __syncthreads();

        #pragma unroll
        for (int kk = 0; kk < 8; kk++) {
            float4 a0 = *reinterpret_cast<const float4*>(&As[kk][ty * 4]);
            float4 a1 = *reinterpret_cast<const float4*>(&As[kk][64 + ty * 4]);
            float4 b0 = *reinterpret_cast<const float4*>(&Bs[kk][tx * 4]);
            float4 b1 = *reinterpret_cast<const float4*>(&Bs[kk][64 + tx * 4]);
            float a[8] = {a0.x, a0.y, a0.z, a0.w, a1.x, a1.y, a1.z, a1.w};
            float bb[8] = {b0.x, b0.y, b0.z, b0.w, b1.x, b1.y, b1.z, b1.w};
            #pragma unroll
            for (int i = 0; i < 8; i++)
                #pragma unroll
                for (int j = 0; j < 8; j++)
                    acc[i][j] = fmaf(a[i], bb[j], acc[i][j]);
        }
        __syncthreads();
    }

    __half* P = g_Pf + (size_t)b * C_DIM * C_DIM;
    #pragma unroll
    for (int i = 0; i < 8; i++) {
        int r = m0 + ((i < 4) ? (ty * 4 + i) : (64 + ty * 4 + (i - 4)));
        #pragma unroll
        for (int jh = 0; jh < 2; jh++) {
            int cbase = n0 + ((jh == 0) ? (tx * 4) : (64 + tx * 4));
            __half h4[4];
            #pragma unroll
            for (int u = 0; u < 4; u++)
                h4[u] = __float2half(acc[i][jh * 4 + u]);
            *reinterpret_cast<uint2*>(P + (size_t)r * C_DIM + cbase) =
                *reinterpret_cast<const uint2*>(h4);
        }
    }
}

// ---------------------------------------------------------------------------
// ob[b][c] = sum_d att[b][d][c] * vb[d]
// ---------------------------------------------------------------------------
__global__ __launch_bounds__(128) void ob_kernel(const float* __restrict__ vb)
{
    const int b = blockIdx.x;
    const int c = blockIdx.y * 128 + threadIdx.x;
    const float* att = g_att + (size_t)b * C_DIM * C_DIM;
    float s = 0.f;
    for (int d = 0; d < C_DIM; d++)
        s = fmaf(att[(size_t)d * C_DIM + c], vb[d], s);
    g_ob[(size_t)b * C_DIM + c] = s;
}

// ---------------------------------------------------------------------------
extern "C" void kernel_launch(void* const* d_in, const int* in_sizes, int n_in,
                              void* d_out, int out_size)
{
    const float* x  = (const float*)d_in[0];
    const float* q  = (const float*)d_in[1];
    const float* kw = (const float*)d_in[2];
    const float* kb = (const float*)d_in[3];
    const float* vw = (const float*)d_in[4];
    const float* vb = (const float*)d_in[5];
    const float* gm = (const float*)d_in[6];
    float* y = (float*)d_out;

    cudaFuncSetAttribute(m1_mma,
                         cudaFuncAttributeMaxDynamicSharedMemorySize, SMEM_TOTAL);
    cudaFuncSetAttribute(out_mma,
                         cudaFuncAttributeMaxDynamicSharedMemorySize, SMEM_OUT);

    split_q_kernel<<<C_DIM, 256>>>(q);
    split_x_kernel<<<dim3(N_DIM / 64, C_DIM / 64, B_DIM), 256>>>(x);

    // split-K: blockIdx.z = b*2 + half -> 256 CTAs
    m1_mma<<<dim3(C_DIM / 128, C_DIM / 128, B_DIM * 2), 256, SMEM_TOTAL>>>();

    // fused energy + softmax: 32 c-rows x full 512 d per CTA
    e_softmax<<<dim3(C_DIM / 32, B_DIM), 256>>>(kw, kb);

    dim3 g2(C_DIM / 128, C_DIM / 128, B_DIM);
    p_gemm<<<g2, 256>>>(vw);

    dim3 g3(B_DIM, C_DIM / 128);
    ob_kernel<<<g3, 128>>>(vb);

    out_mma<<<dim3(N_DIM / 128, C_DIM / 128, B_DIM), 256, SMEM_OUT>>>(x, gm, y);
}

// round 15
// speedup vs baseline: 1.6930x; 1.6930x over previous
#include <cuda_runtime.h>
#include <cuda_bf16.h>
#include <cuda_fp16.h>
#include <math.h>
#include <stdint.h>

// Problem dims (fixed by the reference)
#define B_DIM 8
#define C_DIM 512
#define N_DIM 4096   // W*H = 64*64
#define HALF_N 2048  // split-K half for m1

#define KC 32        // k-chunk
#define LDT 40       // smem tile row stride in bf16 (pad 32 -> 40, conflict-free ldmatrix)
#define TILE_BYTES (128 * LDT * 2)        // 10240
#define STAGE_BYTES (4 * TILE_BYTES)      // 40960 (Ah, Al, Bh, Bl)
#define SMEM_TOTAL (2 * STAGE_BYTES)      // 81920  (m1)
#define STAGE2_BYTES (2 * TILE_BYTES)     // 20480 (A, B) fp16 single-term
#define SMEM_OUT (2 * STAGE2_BYTES)       // 40960  (out)

// ---------------------------------------------------------------------------
// Scratch (device globals — no allocation allowed)
// ---------------------------------------------------------------------------
__device__ __align__(16) __nv_bfloat16 g_xh[(size_t)B_DIM * C_DIM * N_DIM];  // x hi   [b][c][n]
__device__ __align__(16) __nv_bfloat16 g_xl[(size_t)B_DIM * C_DIM * N_DIM];  // x lo
__device__ __align__(16) __half        g_xtf[(size_t)B_DIM * N_DIM * C_DIM]; // x^T fp16 [b][n][c]
__device__ __align__(16) __nv_bfloat16 g_qh[(size_t)C_DIM * N_DIM];          // q hi   [d][n]
__device__ __align__(16) __nv_bfloat16 g_ql[(size_t)C_DIM * N_DIM];          // q lo
__device__ __align__(16) __half        g_Pf[(size_t)B_DIM * C_DIM * C_DIM];  // P fp16 [b][c][e]
__device__ float g_M1[(size_t)2 * B_DIM * C_DIM * C_DIM];   // split-K halves [h][b][c][d]
__device__ float g_E[(size_t)B_DIM * C_DIM * C_DIM];
__device__ float g_att[(size_t)B_DIM * C_DIM * C_DIM];
__device__ float g_ob[(size_t)B_DIM * C_DIM];
__device__ float g_qs[C_DIM];

// ---------------------------------------------------------------------------
// PTX helpers (arch-generic: ldmatrix / mma.sync / cp.async)
// ---------------------------------------------------------------------------
__device__ __forceinline__ uint32_t smem_u32(const void* p) {
    uint32_t a;
    asm("{ .reg .u64 t; cvta.to.shared.u64 t, %1; cvt.u32.u64 %0, t; }"
        : "=r"(a) : "l"(p));
    return a;
}

__device__ __forceinline__ void ldsm4(uint32_t r[4], uint32_t addr) {
    asm volatile("ldmatrix.sync.aligned.m8n8.x4.shared.b16 {%0,%1,%2,%3}, [%4];"
                 : "=r"(r[0]), "=r"(r[1]), "=r"(r[2]), "=r"(r[3]) : "r"(addr));
}

__device__ __forceinline__ void mma16816(float c[4], const uint32_t a[4],
                                         const uint32_t b[2]) {
    asm volatile(
        "mma.sync.aligned.m16n8k16.row.col.f32.bf16.bf16.f32 "
        "{%0,%1,%2,%3}, {%4,%5,%6,%7}, {%8,%9}, {%0,%1,%2,%3};"
        : "+f"(c[0]), "+f"(c[1]), "+f"(c[2]), "+f"(c[3])
        : "r"(a[0]), "r"(a[1]), "r"(a[2]), "r"(a[3]), "r"(b[0]), "r"(b[1]));
}

__device__ __forceinline__ void mma16816_f16(float c[4], const uint32_t a[4],
                                             const uint32_t b[2]) {
    asm volatile(
        "mma.sync.aligned.m16n8k16.row.col.f32.f16.f16.f32 "
        "{%0,%1,%2,%3}, {%4,%5,%6,%7}, {%8,%9}, {%0,%1,%2,%3};"
        : "+f"(c[0]), "+f"(c[1]), "+f"(c[2]), "+f"(c[3])
        : "r"(a[0]), "r"(a[1]), "r"(a[2]), "r"(a[3]), "r"(b[0]), "r"(b[1]));
}

#define CP_ASYNC16(dst, src)                                            \
    asm volatile("cp.async.cg.shared.global [%0], [%1], 16;"            \
                 :: "r"(dst), "l"(src) : "memory")
#define CP_COMMIT asm volatile("cp.async.commit_group;" ::: "memory")
#define CP_WAIT1  asm volatile("cp.async.wait_group 1;" ::: "memory")
#define CP_WAIT0  asm volatile("cp.async.wait_group 0;" ::: "memory")

// Stage one 128 x KC 16-bit tile: 512 x 16B transfers, 2 per thread.
__device__ __forceinline__ void stage_tile(
    uint32_t dstBase, const void* __restrict__ src16,
    int ld, int k0, int tid)
{
    const __nv_bfloat16* src = (const __nv_bfloat16*)src16;
    #pragma unroll
    for (int u = 0; u < 2; u++) {
        int tr  = tid * 2 + u;
        int row = tr >> 2, seg = tr & 3;
        uint32_t dst = dstBase + (uint32_t)row * (LDT * 2) + seg * 16;
        const __nv_bfloat16* s = src + (size_t)row * ld + k0 + seg * 8;
        CP_ASYNC16(dst, (const void*)__cvta_generic_to_global(s));
    }
}

// Compute one KC=32 chunk: 3 bf16 terms (hh, hl, lh) into fp32 acc.
__device__ __forceinline__ void compute_stage(
    uint32_t as_h, uint32_t as_l, uint32_t bs_h, uint32_t bs_l,
    float acc[4][4][4], int lane, int warpM, int warpN)
{
    const int rowA = lane & 15;
    const int colA = (lane >> 4) << 3;
    const int tile = lane >> 3;
    const int rowB = (lane & 7) + ((tile >> 1) << 3);
    const int colB = (tile & 1) << 3;

    #pragma unroll
    for (int ks = 0; ks < KC; ks += 16) {
        uint32_t a[4][4], bb[4][2];
        #pragma unroll
        for (int mi = 0; mi < 4; mi++)
            ldsm4(a[mi], as_h + (uint32_t)(warpM + mi * 16 + rowA) * (LDT * 2)
                               + (colA + ks) * 2);
        #pragma unroll
        for (int njp = 0; njp < 2; njp++) {
            uint32_t r[4];
            ldsm4(r, bs_h + (uint32_t)(warpN + njp * 16 + rowB) * (LDT * 2)
                          + (colB + ks) * 2);
            bb[njp * 2][0] = r[0];  bb[njp * 2][1] = r[1];
            bb[njp * 2 + 1][0] = r[2];  bb[njp * 2 + 1][1] = r[3];
        }
        #pragma unroll
        for (int mi = 0; mi < 4; mi++)
            #pragma unroll
            for (int nj = 0; nj < 4; nj++) mma16816(acc[mi][nj], a[mi], bb[nj]);
        {
            uint32_t al[4][4];
            #pragma unroll
            for (int mi = 0; mi < 4; mi++)
                ldsm4(al[mi], as_l + (uint32_t)(warpM + mi * 16 + rowA) * (LDT * 2)
                                   + (colA + ks) * 2);
            #pragma unroll
            for (int mi = 0; mi < 4; mi++)
                #pragma unroll
                for (int nj = 0; nj < 4; nj++) mma16816(acc[mi][nj], al[mi], bb[nj]);
        }
        #pragma unroll
        for (int njp = 0; njp < 2; njp++) {
            uint32_t r[4];
            ldsm4(r, bs_l + (uint32_t)(warpN + njp * 16 + rowB) * (LDT * 2)
                          + (colB + ks) * 2);
            bb[njp * 2][0] = r[0];  bb[njp * 2][1] = r[1];
            bb[njp * 2 + 1][0] = r[2];  bb[njp * 2 + 1][1] = r[3];
        }
        #pragma unroll
        for (int mi = 0; mi < 4; mi++)
            #pragma unroll
            for (int nj = 0; nj < 4; nj++) mma16816(acc[mi][nj], a[mi], bb[nj]);
    }
}

// Single-term fp16 chunk: 16 MMAs per k16.
__device__ __forceinline__ void compute_stage_f16(
    uint32_t as, uint32_t bs, float acc[4][4][4], int lane, int warpM, int warpN)
{
    const int rowA = lane & 15;
    const int colA = (lane >> 4) << 3;
    const int tile = lane >> 3;
    const int rowB = (lane & 7) + ((tile >> 1) << 3);
    const int colB = (tile & 1) << 3;

    #pragma unroll
    for (int ks = 0; ks < KC; ks += 16) {
        uint32_t a[4][4], bb[4][2];
        #pragma unroll
        for (int mi = 0; mi < 4; mi++)
            ldsm4(a[mi], as + (uint32_t)(warpM + mi * 16 + rowA) * (LDT * 2)
                             + (colA + ks) * 2);
        #pragma unroll
        for (int njp = 0; njp < 2; njp++) {
            uint32_t r[4];
            ldsm4(r, bs + (uint32_t)(warpN + njp * 16 + rowB) * (LDT * 2)
                        + (colB + ks) * 2);
            bb[njp * 2][0] = r[0];  bb[njp * 2][1] = r[1];
            bb[njp * 2 + 1][0] = r[2];  bb[njp * 2 + 1][1] = r[3];
        }
        #pragma unroll
        for (int mi = 0; mi < 4; mi++)
            #pragma unroll
            for (int nj = 0; nj < 4; nj++) mma16816_f16(acc[mi][nj], a[mi], bb[nj]);
    }
}

// bf16 3-term mainloop over k-range [kbeg, kbeg+K).
__device__ __forceinline__ void gemm_mainloop(
    uint32_t sb, const __nv_bfloat16* Ah, const __nv_bfloat16* Al,
    const __nv_bfloat16* Bh, const __nv_bfloat16* Bl,
    int lda, int ldb, int kbeg, int K, float acc[4][4][4],
    int tid, int lane, int warpM, int warpN)
{
    const uint32_t st[2] = { sb, sb + STAGE_BYTES };
    const int nk = K / KC;

    stage_tile(st[0],                  Ah, lda, kbeg, tid);
    stage_tile(st[0] + TILE_BYTES,     Al, lda, kbeg, tid);
    stage_tile(st[0] + 2 * TILE_BYTES, Bh, ldb, kbeg, tid);
    stage_tile(st[0] + 3 * TILE_BYTES, Bl, ldb, kbeg, tid);
    CP_COMMIT;

    for (int i = 0; i < nk; i++) {
        if (i + 1 < nk) {
            uint32_t d = st[(i + 1) & 1];
            int k0 = kbeg + (i + 1) * KC;
            stage_tile(d,                  Ah, lda, k0, tid);
            stage_tile(d + TILE_BYTES,     Al, lda, k0, tid);
            stage_tile(d + 2 * TILE_BYTES, Bh, ldb, k0, tid);
            stage_tile(d + 3 * TILE_BYTES, Bl, ldb, k0, tid);
            CP_COMMIT;
            CP_WAIT1;
        } else {
            CP_WAIT0;
        }
        __syncthreads();
        uint32_t s = st[i & 1];
        compute_stage(s, s + TILE_BYTES, s + 2 * TILE_BYTES, s + 3 * TILE_BYTES,
                      acc, lane, warpM, warpN);
        __syncthreads();
    }
}

// ---------------------------------------------------------------------------
// M1[h][b][c][d] = sum_{n in half h} x[b][c][n] * q[d][n]  (split-K HMMA)
// blockIdx.z = b*2 + h
// ---------------------------------------------------------------------------
__global__ __launch_bounds__(256, 2) void m1_mma()
{
    extern __shared__ char smem[];
    const uint32_t sb = smem_u32(smem);
    const int tid = threadIdx.x, lane = tid & 31, wid = tid >> 5;
    const int warpM = (wid >> 2) * 64, warpN = (wid & 3) * 32;
    const int bz = blockIdx.z;
    const int b = bz >> 1, h = bz & 1;
    const int m0 = blockIdx.y * 128, n0 = blockIdx.x * 128;

    float acc[4][4][4];
    #pragma unroll
    for (int i = 0; i < 4; i++)
        #pragma unroll
        for (int j = 0; j < 4; j++)
            #pragma unroll
            for (int k = 0; k < 4; k++) acc[i][j][k] = 0.f;

    const size_t xo = (size_t)b * C_DIM * N_DIM + (size_t)m0 * N_DIM;
    gemm_mainloop(sb, g_xh + xo, g_xl + xo,
                  g_qh + (size_t)n0 * N_DIM, g_ql + (size_t)n0 * N_DIM,
                  N_DIM, N_DIM, h * HALF_N, HALF_N, acc, tid, lane, warpM, warpN);

    const int gid = lane >> 2, tig = lane & 3;
    float* C = g_M1 + ((size_t)(h * B_DIM + b) * C_DIM + m0) * C_DIM + n0;
    #pragma unroll
    for (int mi = 0; mi < 4; mi++) {
        #pragma unroll
        for (int nj = 0; nj < 4; nj++) {
            int r = warpM + mi * 16 + gid;
            int c = warpN + nj * 8 + 2 * tig;
            *reinterpret_cast<float2*>(C + (size_t)r * C_DIM + c) =
                make_float2(acc[mi][nj][0], acc[mi][nj][1]);
            *reinterpret_cast<float2*>(C + (size_t)(r + 8) * C_DIM + c) =
                make_float2(acc[mi][nj][2], acc[mi][nj][3]);
        }
    }
}

// ---------------------------------------------------------------------------
// y[b][c][n] = gamma*(sum_e P[b][c][e]*x[b][e][n] + ob[b][c]) + x[b][c][n]
// Single-term fp16 HMMA (error ~2^-12, not softmax-amplified).
// ---------------------------------------------------------------------------
__global__ __launch_bounds__(256, 2) void out_mma(
    const float* __restrict__ x, const float* __restrict__ gamma,
    float* __restrict__ y)
{
    extern __shared__ char smem[];
    const uint32_t sb = smem_u32(smem);
    const int tid = threadIdx.x, lane = tid & 31, wid = tid >> 5;
    const int warpM = (wid >> 2) * 64, warpN = (wid & 3) * 32;
    const int b = blockIdx.z, m0 = blockIdx.y * 128, n0 = blockIdx.x * 128;

    float acc[4][4][4];
    #pragma unroll
    for (int i = 0; i < 4; i++)
        #pragma unroll
        for (int j = 0; j < 4; j++)
            #pragma unroll
            for (int k = 0; k < 4; k++) acc[i][j][k] = 0.f;

    const __half* A = g_Pf  + (size_t)b * C_DIM * C_DIM + (size_t)m0 * C_DIM;
    const __half* B = g_xtf + (size_t)b * N_DIM * C_DIM + (size_t)n0 * C_DIM;

    const uint32_t st[2] = { sb, sb + STAGE2_BYTES };
    const int nk = C_DIM / KC;   // 16

    stage_tile(st[0],              A, C_DIM, 0, tid);
    stage_tile(st[0] + TILE_BYTES, B, C_DIM, 0, tid);
    CP_COMMIT;

    for (int i = 0; i < nk; i++) {
        if (i + 1 < nk) {
            uint32_t d = st[(i + 1) & 1];
            int k0 = (i + 1) * KC;
            stage_tile(d,              A, C_DIM, k0, tid);
            stage_tile(d + TILE_BYTES, B, C_DIM, k0, tid);
            CP_COMMIT;
            CP_WAIT1;
        } else {
            CP_WAIT0;
        }
        __syncthreads();
        uint32_t s = st[i & 1];
        compute_stage_f16(s, s + TILE_BYTES, acc, lane, warpM, warpN);
        __syncthreads();
    }

    const int gid = lane >> 2, tig = lane & 3;
    const float g = *gamma;
    const float* xb = x + (size_t)b * C_DIM * N_DIM;
    float*       yb = y + (size_t)b * C_DIM * N_DIM;
    #pragma unroll
    for (int mi = 0; mi < 4; mi++) {
        #pragma unroll
        for (int nj = 0; nj < 4; nj++) {
            int r = m0 + warpM + mi * 16 + gid;
            int c = n0 + warpN + nj * 8 + 2 * tig;
            #pragma unroll
            for (int h = 0; h < 2; h++) {
                int rr = r + h * 8;
                float ob = g_ob[(size_t)b * C_DIM + rr];
                float2 xv = *reinterpret_cast<const float2*>(
                    xb + (size_t)rr * N_DIM + c);
                float2 o;
                o.x = fmaf(g, acc[mi][nj][h * 2 + 0] + ob, xv.x);
                o.y = fmaf(g, acc[mi][nj][h * 2 + 1] + ob, xv.y);
                *reinterpret_cast<float2*>(yb + (size_t)rr * N_DIM + c) = o;
            }
        }
    }
}

// ---------------------------------------------------------------------------
// split_x: x -> bf16 hi/lo [c][n] + fp16 x^T [n][c].  64x64 tiles, fully
// vectorized: float4 reads, 16B stores.
// ---------------------------------------------------------------------------
__global__ __launch_bounds__(256) void split_x_kernel(const float* __restrict__ x)
{
    __shared__ float sx[64][65];
    const int b  = blockIdx.z;
    const int c0 = blockIdx.y * 64;
    const int n0 = blockIdx.x * 64;
    const int t  = threadIdx.x;
    const int r  = t >> 2;          // 0..63
    const int gcol = (t & 3) * 16;  // 0,16,32,48

    // Phase A: read 16 floats of row (c0+r), emit hi/lo, stash fp32.
    {
        const float* src = x + ((size_t)b * C_DIM + c0 + r) * N_DIM + n0 + gcol;
        __nv_bfloat16 h16[16], l16[16];
        #pragma unroll
        for (int u = 0; u < 4; u++) {
            float4 v = *reinterpret_cast<const float4*>(src + u * 4);
            float vv[4] = {v.x, v.y, v.z, v.w};
            #pragma unroll
            for (int k = 0; k < 4; k++) {
                float f = vv[k];
                __nv_bfloat16 hh = __float2bfloat16(f);
                h16[u * 4 + k] = hh;
                l16[u * 4 + k] = __float2bfloat16(f - __bfloat162float(hh));
                sx[r][gcol + u * 4 + k] = f;
            }
        }
        size_t o = ((size_t)b * C_DIM + c0 + r) * N_DIM + n0 + gcol;
        *reinterpret_cast<uint4*>(g_xh + o)     = reinterpret_cast<const uint4*>(h16)[0];
        *reinterpret_cast<uint4*>(g_xh + o + 8) = reinterpret_cast<const uint4*>(h16)[1];
        *reinterpret_cast<uint4*>(g_xl + o)     = reinterpret_cast<const uint4*>(l16)[0];
        *reinterpret_cast<uint4*>(g_xl + o + 8) = reinterpret_cast<const uint4*>(l16)[1];
    }
    __syncthreads();

    // Phase B: transposed — row r is now n-index, cols are c. fp16 out.
    {
        __half f16[16];
        #pragma unroll
        for (int k = 0; k < 16; k++)
            f16[k] = __float2half(sx[gcol + k][r]);
        size_t o = ((size_t)b * N_DIM + n0 + r) * C_DIM + c0 + gcol;
        *reinterpret_cast<uint4*>(g_xtf + o)     = reinterpret_cast<const uint4*>(f16)[0];
        *reinterpret_cast<uint4*>(g_xtf + o + 8) = reinterpret_cast<const uint4*>(f16)[1];
    }
}

// ---------------------------------------------------------------------------
// split_q + qsum fused: one block per q row d. hi/lo bf16 + row sum.
// ---------------------------------------------------------------------------
__global__ __launch_bounds__(256) void split_q_kernel(const float* __restrict__ q)
{
    const int d = blockIdx.x;
    const int t = threadIdx.x;
    const float* row = q + (size_t)d * N_DIM + t * 16;

    __nv_bfloat16 h16[16], l16[16];
    float s = 0.f;
    #pragma unroll
    for (int u = 0; u < 4; u++) {
        float4 v = *reinterpret_cast<const float4*>(row + u * 4);
        float vv[4] = {v.x, v.y, v.z, v.w};
        #pragma unroll
        for (int k = 0; k < 4; k++) {
            float f = vv[k];
            s += f;
            __nv_bfloat16 hh = __float2bfloat16(f);
            h16[u * 4 + k] = hh;
            l16[u * 4 + k] = __float2bfloat16(f - __bfloat162float(hh));
        }
    }
    size_t o = (size_t)d * N_DIM + t * 16;
    *reinterpret_cast<uint4*>(g_qh + o)     = reinterpret_cast<const uint4*>(h16)[0];
    *reinterpret_cast<uint4*>(g_qh + o + 8) = reinterpret_cast<const uint4*>(h16)[1];
    *reinterpret_cast<uint4*>(g_ql + o)     = reinterpret_cast<const uint4*>(l16)[0];
    *reinterpret_cast<uint4*>(g_ql + o + 8) = reinterpret_cast<const uint4*>(l16)[1];

    #pragma unroll
    for (int o2 = 16; o2 > 0; o2 >>= 1) s += __shfl_xor_sync(0xffffffffu, s, o2);
    __shared__ float red[8];
    if ((t & 31) == 0) red[t >> 5] = s;
    __syncthreads();
    if (t == 0) {
        float tt = 0.f;
        #pragma unroll
        for (int i = 0; i < 8; i++) tt += red[i];
        g_qs[d] = tt;
    }
}

// ---------------------------------------------------------------------------
// E[b][c][d] = sum_e Kw[c][e] * (M1a+M1b)[b][e][d] + kb[c] * s[d]  (fp32)
// ---------------------------------------------------------------------------
__global__ __launch_bounds__(256) void e_gemm(
    const float* __restrict__ kw, const float* __restrict__ kb)
{
    __shared__ float As[8][128];
    __shared__ float Bs[8][128];

    const int b  = blockIdx.z;
    const int m0 = blockIdx.y * 128;
    const int n0 = blockIdx.x * 128;
    const int tid = threadIdx.x;
    const int tx = tid & 15;
    const int ty = tid >> 4;

    const float* M1a = g_M1 + (size_t)b * C_DIM * C_DIM;
    const float* M1b = g_M1 + (size_t)(B_DIM + b) * C_DIM * C_DIM;

    float acc[8][8];
    #pragma unroll
    for (int i = 0; i < 8; i++)
        #pragma unroll
        for (int j = 0; j < 8; j++) acc[i][j] = 0.f;

    for (int k0 = 0; k0 < C_DIM; k0 += 8) {
        {
            int m   = tid >> 1;
            int kkh = (tid & 1) * 4;
            float4 av = *reinterpret_cast<const float4*>(
                kw + (size_t)(m0 + m) * C_DIM + k0 + kkh);
            As[kkh + 0][m] = av.x;  As[kkh + 1][m] = av.y;
            As[kkh + 2][m] = av.z;  As[kkh + 3][m] = av.w;
        }
        {
            int kk = tid >> 5;
            int c4 = (tid & 31) * 4;
            size_t off = (size_t)(k0 + kk) * C_DIM + n0 + c4;
            float4 v0 = *reinterpret_cast<const float4*>(M1a + off);
            float4 v1 = *reinterpret_cast<const float4*>(M1b + off);
            float4 bv;
            bv.x = v0.x + v1.x;  bv.y = v0.y + v1.y;
            bv.z = v0.z + v1.z;  bv.w = v0.w + v1.w;
            *reinterpret_cast<float4*>(&Bs[kk][c4]) = bv;
        }
        __syncthreads();

        #pragma unroll
        for (int kk = 0; kk < 8; kk++) {
            float4 a0 = *reinterpret_cast<const float4*>(&As[kk][ty * 4]);
            float4 a1 = *reinterpret_cast<const float4*>(&As[kk][64 + ty * 4]);
            float4 b0 = *reinterpret_cast<const float4*>(&Bs[kk][tx * 4]);
            float4 b1 = *reinterpret_cast<const float4*>(&Bs[kk][64 + tx * 4]);
            float a[8] = {a0.x, a0.y, a0.z, a0.w, a1.x, a1.y, a1.z, a1.w};
            float bb[8] = {b0.x, b0.y, b0.z, b0.w, b1.x, b1.y, b1.z, b1.w};
            #pragma unroll
            for (int i = 0; i < 8; i++)
                #pragma unroll
                for (int j = 0; j < 8; j++)
                    acc[i][j] = fmaf(a[i], bb[j], acc[i][j]);
        }
        __syncthreads();
    }

    float* E = g_E + (size_t)b * C_DIM * C_DIM;
    #pragma unroll
    for (int i = 0; i < 8; i++) {
        int r = m0 + ((i < 4) ? (ty * 4 + i) : (64 + ty * 4 + (i - 4)));
        float bias = kb[r];
        #pragma unroll
        for (int jh = 0; jh < 2; jh++) {
            int cbase = n0 + ((jh == 0) ? (tx * 4) : (64 + tx * 4));
            float4 o4;
            o4.x = fmaf(bias, g_qs[cbase + 0], acc[i][jh * 4 + 0]);
            o4.y = fmaf(bias, g_qs[cbase + 1], acc[i][jh * 4 + 1]);
            o4.z = fmaf(bias, g_qs[cbase + 2], acc[i][jh * 4 + 2]);
            o4.w = fmaf(bias, g_qs[cbase + 3], acc[i][jh * 4 + 3]);
            *reinterpret_cast<float4*>(E + (size_t)r * C_DIM + cbase) = o4;
        }
    }
}

// ---------------------------------------------------------------------------
// Softmax over last axis (d, 512 values) for each (b, c) row.
// ---------------------------------------------------------------------------
__global__ __launch_bounds__(256) void softmax_rows()
{
    const int row = blockIdx.x;
    const float* e = g_E + (size_t)row * C_DIM;
    float* a = g_att + (size_t)row * C_DIM;
    const int t = threadIdx.x;

    float v0 = e[t], v1 = e[t + 256];
    float m = fmaxf(v0, v1);
    __shared__ float red[8];

    #pragma unroll
    for (int o = 16; o > 0; o >>= 1) m = fmaxf(m, __shfl_xor_sync(0xffffffffu, m, o));
    if ((t & 31) == 0) red[t >> 5] = m;
    __syncthreads();
    if (t < 32) {
        float mm = (t < 8) ? red[t] : -INFINITY;
        #pragma unroll
        for (int o = 4; o > 0; o >>= 1) mm = fmaxf(mm, __shfl_xor_sync(0xffffffffu, mm, o));
        if (t == 0) red[0] = mm;
    }
    __syncthreads();
    const float mm = red[0];

    float e0 = expf(v0 - mm), e1 = expf(v1 - mm);
    float s = e0 + e1;
    #pragma unroll
    for (int o = 16; o > 0; o >>= 1) s += __shfl_xor_sync(0xffffffffu, s, o);
    __syncthreads();
    if ((t & 31) == 0) red[t >> 5] = s;
    __syncthreads();
    if (t < 32) {
        float ss = (t < 8) ? red[t] : 0.f;
        #pragma unroll
        for (int o = 4; o > 0; o >>= 1) ss += __shfl_xor_sync(0xffffffffu, ss, o);
        if (t == 0) red[0] = ss;
    }
    __syncthreads();
    const float inv = 1.0f / red[0];
    a[t]       = e0 * inv;
    a[t + 256] = e1 * inv;
}

// ---------------------------------------------------------------------------
// P[b][c][e] = sum_d att[b][d][c] * Vw[d][e]  (fp32 SGEMM, fp16 epilogue)
// ---------------------------------------------------------------------------
__global__ __launch_bounds__(256) void p_gemm(const float* __restrict__ vw)
{
    __shared__ float As[8][128];
    __shared__ float Bs[8][128];

    const int b  = blockIdx.z;
    const int m0 = blockIdx.y * 128;
    const int n0 = blockIdx.x * 128;
    const int tid = threadIdx.x;
    const int tx = tid & 15;
    const int ty = tid >> 4;

    const float* att = g_att + (size_t)b * C_DIM * C_DIM;

    float acc[8][8];
    #pragma unroll
    for (int i = 0; i < 8; i++)
        #pragma unroll
        for (int j = 0; j < 8; j++) acc[i][j] = 0.f;

    for (int k0 = 0; k0 < C_DIM; k0 += 8) {
        {
            int kk = tid >> 5;
            int m4 = (tid & 31) * 4;
            float4 av = *reinterpret_cast<const float4*>(
                att + (size_t)(k0 + kk) * C_DIM + m0 + m4);
            *reinterpret_cast<float4*>(&As[kk][m4]) = av;
        }
        {
            int kk = tid >> 5;
            int c4 = (tid & 31) * 4;
            float4 bv = *reinterpret_cast<const float4*>(
                vw + (size_t)(k0 + kk) * C_DIM + n0 + c4);
            *reinterpret_cast<float4*>(&Bs[kk][c4]) = bv;
        }
        __syncthreads();

        #pragma unroll
        for (int kk = 0; kk < 8; kk++) {
            float4 a0 = *reinterpret_cast<const float4*>(&As[kk][ty * 4]);
            float4 a1 = *reinterpret_cast<const float4*>(&As[kk][64 + ty * 4]);
            float4 b0 = *reinterpret_cast<const float4*>(&Bs[kk][tx * 4]);
            float4 b1 = *reinterpret_cast<const float4*>(&Bs[kk][64 + tx * 4]);
            float a[8] = {a0.x, a0.y, a0.z, a0.w, a1.x, a1.y, a1.z, a1.w};
            float bb[8] = {b0.x, b0.y, b0.z, b0.w, b1.x, b1.y, b1.z, b1.w};
            #pragma unroll
            for (int i = 0; i < 8; i++)
                #pragma unroll
                for (int j = 0; j < 8; j++)
                    acc[i][j] = fmaf(a[i], bb[j], acc[i][j]);
        }
        __syncthreads();
    }

    __half* P = g_Pf + (size_t)b * C_DIM * C_DIM;
    #pragma unroll
    for (int i = 0; i < 8; i++) {
        int r = m0 + ((i < 4) ? (ty * 4 + i) : (64 + ty * 4 + (i - 4)));
        #pragma unroll
        for (int jh = 0; jh < 2; jh++) {
            int cbase = n0 + ((jh == 0) ? (tx * 4) : (64 + tx * 4));
            __half h4[4];
            #pragma unroll
            for (int u = 0; u < 4; u++)
                h4[u] = __float2half(acc[i][jh * 4 + u]);
            *reinterpret_cast<uint2*>(P + (size_t)r * C_DIM + cbase) =
                *reinterpret_cast<const uint2*>(h4);
        }
    }
}

// ---------------------------------------------------------------------------
// ob[b][c] = sum_d att[b][d][c] * vb[d]
// ---------------------------------------------------------------------------
__global__ __launch_bounds__(128) void ob_kernel(const float* __restrict__ vb)
{
    const int b = blockIdx.x;
    const int c = blockIdx.y * 128 + threadIdx.x;
    const float* att = g_att + (size_t)b * C_DIM * C_DIM;
    float s = 0.f;
    for (int d = 0; d < C_DIM; d++)
        s = fmaf(att[(size_t)d * C_DIM + c], vb[d], s);
    g_ob[(size_t)b * C_DIM + c] = s;
}

// ---------------------------------------------------------------------------
extern "C" void kernel_launch(void* const* d_in, const int* in_sizes, int n_in,
                              void* d_out, int out_size)
{
    const float* x  = (const float*)d_in[0];
    const float* q  = (const float*)d_in[1];
    const float* kw = (const float*)d_in[2];
    const float* kb = (const float*)d_in[3];
    const float* vw = (const float*)d_in[4];
    const float* vb = (const float*)d_in[5];
    const float* gm = (const float*)d_in[6];
    float* y = (float*)d_out;

    cudaFuncSetAttribute(m1_mma,
                         cudaFuncAttributeMaxDynamicSharedMemorySize, SMEM_TOTAL);
    cudaFuncSetAttribute(out_mma,
                         cudaFuncAttributeMaxDynamicSharedMemorySize, SMEM_OUT);

    split_q_kernel<<<C_DIM, 256>>>(q);
    split_x_kernel<<<dim3(N_DIM / 64, C_DIM / 64, B_DIM), 256>>>(x);

    // split-K: blockIdx.z = b*2 + half -> 256 CTAs
    m1_mma<<<dim3(C_DIM / 128, C_DIM / 128, B_DIM * 2), 256, SMEM_TOTAL>>>();

    dim3 g2(C_DIM / 128, C_DIM / 128, B_DIM);
    e_gemm<<<g2, 256>>>(kw, kb);

    softmax_rows<<<B_DIM * C_DIM, 256>>>();

    p_gemm<<<g2, 256>>>(vw);

    dim3 g3(B_DIM, C_DIM / 128);
    ob_kernel<<<g3, 128>>>(vb);

    out_mma<<<dim3(N_DIM / 128, C_DIM / 128, B_DIM), 256, SMEM_OUT>>>(x, gm, y);
}